// round 7
// baseline (speedup 1.0000x reference)
#include <cuda_runtime.h>

// WindowAttention fused kernel, fp32 packed fma.rn.f32x2 (sm_103a).
// R4: 512 threads/CTA (16 warps), register-block transposes, LDN=68,
//     double-buffered qkv_w staging in GEMM1 (one barrier per chunk).

#define SCALE_F 0.17677669529663687f   // 32^-0.5

#define LDN 68     // leading dim for k-major [*][64] arrays (float4-aligned rows)
#define LDV 132    // v row-major [64][128] padded
#define LDW 260    // staged qkv_w chunk [16][256] padded
#define LDP 132    // p_t [128][128] padded

#define OFF_QT 0                        // q_t [128][LDN] (o_t aliases after GEMM2)
#define OFF_KT (128*LDN)                // k_t [128][LDN]
#define OFF_V  (2*128*LDN)              // v   [64][LDV]
#define OFF_AT (OFF_V + 64*LDV)         // y_t [128][LDN] -> attn_t [256][LDN] -> p_t [128][LDP]
#define OFF_W  (OFF_AT + 128*LDN)       // W double buffer: 2 x [16][LDW] (upper attn region)
#define OFF_SC (OFF_AT + 256*LDN)       // softmax scratch [2][256]
#define SMEM_FLOATS (OFF_SC + 512)
#define SMEM_BYTES  (SMEM_FLOATS * 4)   // 175104 B

typedef unsigned long long u64;

__device__ __forceinline__ u64 pk2(float v) {
    u64 r; asm("mov.b64 %0, {%1, %1};" : "=l"(r) : "f"(v)); return r;
}
__device__ __forceinline__ u64 f2fma(u64 a, u64 b, u64 c) {
    u64 d; asm("fma.rn.f32x2 %0, %1, %2, %3;" : "=l"(d) : "l"(a), "l"(b), "l"(c)); return d;
}
__device__ __forceinline__ u64 f2add(u64 a, u64 b) {
    u64 d; asm("add.rn.f32x2 %0, %1, %2;" : "=l"(d) : "l"(a), "l"(b)); return d;
}
__device__ __forceinline__ void upk2(u64 v, float& lo, float& hi) {
    asm("mov.b64 {%0, %1}, %2;" : "=f"(lo), "=f"(hi) : "l"(v));
}
__device__ __forceinline__ u64 lds2(const float* p) {
    return *reinterpret_cast<const u64*>(p);
}

__global__ void __launch_bounds__(512, 1)
wattn_kernel(const float* __restrict__ x, const float* __restrict__ y,
             const float* __restrict__ P, const float* __restrict__ maskp,
             const float* __restrict__ qkv_w, const float* __restrict__ qkv_b,
             const float* __restrict__ proj_w, const float* __restrict__ proj_b,
             const float* __restrict__ lam_p, float* __restrict__ out)
{
    extern __shared__ float sm[];
    const int b   = blockIdx.x;
    const int tid = threadIdx.x;

    // ===== Phase 0: register 4x4 block transposes =====
    // x -> q_t[(32h+d)][n] scaled  (pairs over n for GEMM2 A-operand)
    {
        const int h = tid >> 7, nb = (tid >> 3) & 15, db = tid & 7;
        const float* xb = x + (size_t)b * 8192 + h * 2048 + db * 4;
        float4 r0 = *(const float4*)(xb + (4 * nb + 0) * 32);
        float4 r1 = *(const float4*)(xb + (4 * nb + 1) * 32);
        float4 r2 = *(const float4*)(xb + (4 * nb + 2) * 32);
        float4 r3 = *(const float4*)(xb + (4 * nb + 3) * 32);
        float* qb = &sm[OFF_QT + (32 * h + 4 * db) * LDN + 4 * nb];
        *(float4*)(qb + 0 * LDN) = make_float4(r0.x*SCALE_F, r1.x*SCALE_F, r2.x*SCALE_F, r3.x*SCALE_F);
        *(float4*)(qb + 1 * LDN) = make_float4(r0.y*SCALE_F, r1.y*SCALE_F, r2.y*SCALE_F, r3.y*SCALE_F);
        *(float4*)(qb + 2 * LDN) = make_float4(r0.z*SCALE_F, r1.z*SCALE_F, r2.z*SCALE_F, r3.z*SCALE_F);
        *(float4*)(qb + 3 * LDN) = make_float4(r0.w*SCALE_F, r1.w*SCALE_F, r2.w*SCALE_F, r3.w*SCALE_F);
    }
    // y -> y_t[k][n]  (pairs over n for GEMM1 A-operand)
    {
        const int nb = tid & 15, kb = tid >> 4;       // kb 0..31
        const float* yb = y + (size_t)b * 8192 + kb * 4;
        float4 r0 = *(const float4*)(yb + (4 * nb + 0) * 128);
        float4 r1 = *(const float4*)(yb + (4 * nb + 1) * 128);
        float4 r2 = *(const float4*)(yb + (4 * nb + 2) * 128);
        float4 r3 = *(const float4*)(yb + (4 * nb + 3) * 128);
        float* yt = &sm[OFF_AT + (4 * kb) * LDN + 4 * nb];
        *(float4*)(yt + 0 * LDN) = make_float4(r0.x, r1.x, r2.x, r3.x);
        *(float4*)(yt + 1 * LDN) = make_float4(r0.y, r1.y, r2.y, r3.y);
        *(float4*)(yt + 2 * LDN) = make_float4(r0.z, r1.z, r2.z, r3.z);
        *(float4*)(yt + 3 * LDN) = make_float4(r0.w, r1.w, r2.w, r3.w);
    }

    // ===== GEMM1: kv[n][c] = sum_k y_t[k][n] * qkv_w[c][k] + qkv_b[c] =====
    // 64 x 256, K=128. Thread tile 8n x 4c. Double-buffered weight staging.
    {
        const int tc = tid >> 3, tr = tid & 7;
        const int c0 = tc << 2, r0 = tr << 3;
        const int cw = tid >> 1, hf = tid & 1;
        const float* wsrc = qkv_w + cw * 128 + 8 * hf;
        u64 acc[4][4];
        #pragma unroll
        for (int p = 0; p < 4; ++p)
            #pragma unroll
            for (int cc = 0; cc < 4; ++cc) acc[p][cc] = 0ull;

        // prefetch + stage chunk 0 into buffer 0
        {
            float4 w0 = *(const float4*)(wsrc);
            float4 w1 = *(const float4*)(wsrc + 4);
            float wv[8] = {w0.x,w0.y,w0.z,w0.w, w1.x,w1.y,w1.z,w1.w};
            #pragma unroll
            for (int jj = 0; jj < 8; ++jj)
                sm[OFF_W + (8 * hf + jj) * LDW + cw] = wv[jj];
        }
        __syncthreads();   // phase-0 transposes + W chunk 0 visible

        #pragma unroll 1
        for (int ch = 0; ch < 8; ++ch) {
            const int kk0 = ch << 4;
            const int cur = OFF_W + (ch & 1) * (16 * LDW);
            // prefetch next chunk from global while computing current
            float4 w0, w1;
            if (ch < 7) {
                w0 = *(const float4*)(wsrc + kk0 + 16);
                w1 = *(const float4*)(wsrc + kk0 + 20);
            }
            #pragma unroll 4
            for (int j = 0; j < 16; ++j) {
                const float* ar = &sm[OFF_AT + (kk0 + j) * LDN + r0];
                u64 a0 = lds2(ar), a1 = lds2(ar + 2), a2 = lds2(ar + 4), a3 = lds2(ar + 6);
                float4 bv = *(const float4*)&sm[cur + j * LDW + c0];
                float bs[4] = {bv.x, bv.y, bv.z, bv.w};
                #pragma unroll
                for (int cc = 0; cc < 4; ++cc) {
                    u64 bb = pk2(bs[cc]);
                    acc[0][cc] = f2fma(a0, bb, acc[0][cc]);
                    acc[1][cc] = f2fma(a1, bb, acc[1][cc]);
                    acc[2][cc] = f2fma(a2, bb, acc[2][cc]);
                    acc[3][cc] = f2fma(a3, bb, acc[3][cc]);
                }
            }
            if (ch < 7) {
                const int nxt = OFF_W + ((ch + 1) & 1) * (16 * LDW);
                float wv[8] = {w0.x,w0.y,w0.z,w0.w, w1.x,w1.y,w1.z,w1.w};
                #pragma unroll
                for (int jj = 0; jj < 8; ++jj)
                    sm[nxt + (8 * hf + jj) * LDW + cw] = wv[jj];
                __syncthreads();
            }
        }
        float4 b4 = *(const float4*)(qkv_b + c0);
        float bias[4] = {b4.x, b4.y, b4.z, b4.w};
        if (c0 < 128) {   // K -> transposed k_t[c][n], keep packed pairs
            #pragma unroll
            for (int cc = 0; cc < 4; ++cc) {
                u64 bb = pk2(bias[cc]);
                #pragma unroll
                for (int p = 0; p < 4; ++p)
                    *(u64*)&sm[OFF_KT + (c0 + cc) * LDN + r0 + 2 * p] = f2add(acc[p][cc], bb);
            }
        } else {          // V -> row-major v[n][c']
            #pragma unroll
            for (int cc = 0; cc < 4; ++cc) {
                int c = c0 + cc - 128;
                #pragma unroll
                for (int p = 0; p < 4; ++p) {
                    float lo, hi; upk2(acc[p][cc], lo, hi);
                    sm[OFF_V + (r0 + 2 * p    ) * LDV + c] = lo + bias[cc];
                    sm[OFF_V + (r0 + 2 * p + 1) * LDV + c] = hi + bias[cc];
                }
            }
        }
    }
    __syncthreads();

    // ===== GEMM2: attn_t[h*64+m][n] = sum_d q_t[32h+d][n] * k_t[32h+d][m] =====
    // Thread tile 8n x 4m, 128 threads per head.
    {
        const int h = tid >> 7, rest = tid & 127;
        const int mg = rest >> 3, tr = rest & 7;
        const int m0 = mg << 2, r0 = tr << 3;
        u64 acc[4][4];
        #pragma unroll
        for (int p = 0; p < 4; ++p)
            #pragma unroll
            for (int cc = 0; cc < 4; ++cc) acc[p][cc] = 0ull;
        #pragma unroll 8
        for (int d = 0; d < 32; ++d) {
            const int row = (h << 5) + d;
            const float* ar = &sm[OFF_QT + row * LDN + r0];
            u64 a0 = lds2(ar), a1 = lds2(ar + 2), a2 = lds2(ar + 4), a3 = lds2(ar + 6);
            float4 bv = *(const float4*)&sm[OFF_KT + row * LDN + m0];
            float bs[4] = {bv.x, bv.y, bv.z, bv.w};
            #pragma unroll
            for (int cc = 0; cc < 4; ++cc) {
                u64 bb = pk2(bs[cc]);
                acc[0][cc] = f2fma(a0, bb, acc[0][cc]);
                acc[1][cc] = f2fma(a1, bb, acc[1][cc]);
                acc[2][cc] = f2fma(a2, bb, acc[2][cc]);
                acc[3][cc] = f2fma(a3, bb, acc[3][cc]);
            }
        }
        #pragma unroll
        for (int cc = 0; cc < 4; ++cc) {
            const int row = (h << 6) + m0 + cc;
            #pragma unroll
            for (int p = 0; p < 4; ++p)
                *(u64*)&sm[OFF_AT + row * LDN + r0 + 2 * p] = acc[p][cc];
        }
    }
    __syncthreads();

    // ===== Softmax over m with mask + lambda*P added; 2 threads per column =====
    {
        const int col = tid & 255, half = tid >> 8;
        const int h = col >> 6, n = col & 63;
        const int m0 = half << 5;
        const float lam = lam_p[0];
        const int w = b & 2047;
        const float4* Pr = (const float4*)(P + ((((size_t)b * 4 + h) * 64 + n) * 64) + m0);
        const float4* Mr = (const float4*)(maskp + (((size_t)w * 64 + n) * 64) + m0);
        const int base = OFF_AT + ((h << 6) + m0) * LDN + n;
        float v[32];
        float s = 0.f;
        #pragma unroll
        for (int q = 0; q < 8; ++q) {
            float4 pv = Pr[q];
            float4 mv = Mr[q];
            float t0 = sm[base + (4*q+0)*LDN] + mv.x + lam * pv.x;
            float t1 = sm[base + (4*q+1)*LDN] + mv.y + lam * pv.y;
            float t2 = sm[base + (4*q+2)*LDN] + mv.z + lam * pv.z;
            float t3 = sm[base + (4*q+3)*LDN] + mv.w + lam * pv.w;
            v[4*q+0] = __expf(t0); v[4*q+1] = __expf(t1);
            v[4*q+2] = __expf(t2); v[4*q+3] = __expf(t3);
            s += v[4*q+0] + v[4*q+1] + v[4*q+2] + v[4*q+3];
        }
        sm[OFF_SC + (half << 8) + col] = s;
        __syncthreads();
        const float inv = 1.0f / (sm[OFF_SC + col] + sm[OFF_SC + 256 + col]);
        #pragma unroll
        for (int m = 0; m < 32; ++m) sm[base + m * LDN] = v[m] * inv;
    }
    __syncthreads();

    // ===== GEMM3: o_t[j][n] = sum_m attn_t[h*64+m][n] * v[m][j], h=j/32 =====
    // Thread tile 4n x 4j; output aliases dead q_t.
    {
        const int nr = tid & 15, jc = tid >> 4;
        const int n0 = nr << 2, j0 = jc << 2, h = jc >> 3;
        u64 acc[2][4];
        #pragma unroll
        for (int p = 0; p < 2; ++p)
            #pragma unroll
            for (int cc = 0; cc < 4; ++cc) acc[p][cc] = 0ull;
        #pragma unroll 8
        for (int m = 0; m < 64; ++m) {
            const float* ar = &sm[OFF_AT + ((h << 6) + m) * LDN + n0];
            u64 a0 = lds2(ar), a1 = lds2(ar + 2);
            float4 bv = *(const float4*)&sm[OFF_V + m * LDV + j0];
            float bs[4] = {bv.x, bv.y, bv.z, bv.w};
            #pragma unroll
            for (int cc = 0; cc < 4; ++cc) {
                u64 bb = pk2(bs[cc]);
                acc[0][cc] = f2fma(a0, bb, acc[0][cc]);
                acc[1][cc] = f2fma(a1, bb, acc[1][cc]);
            }
        }
        #pragma unroll
        for (int cc = 0; cc < 4; ++cc)
            #pragma unroll
            for (int p = 0; p < 2; ++p)
                *(u64*)&sm[OFF_QT + (j0 + cc) * LDN + n0 + 2 * p] = acc[p][cc];
    }
    __syncthreads();

    // ===== Stage proj_w transposed: p_t[j][c] (aliases dead attn region) =====
    {
        const int c = tid >> 2, qq = tid & 3;
        const float* pr = proj_w + c * 128 + qq * 32;
        #pragma unroll
        for (int i = 0; i < 8; ++i) {
            float4 pv = ((const float4*)pr)[i];
            const int j = (qq << 5) + (i << 2);
            sm[OFF_AT + (j    ) * LDP + c] = pv.x;
            sm[OFF_AT + (j + 1) * LDP + c] = pv.y;
            sm[OFF_AT + (j + 2) * LDP + c] = pv.z;
            sm[OFF_AT + (j + 3) * LDP + c] = pv.w;
        }
    }
    __syncthreads();

    // ===== GEMM4: res[n][c] = sum_j o_t[j][n] * p_t[j][c] + proj_b[c] =====
    // Thread tile 4n x 4c.
    {
        const int nr = tid & 15, cg = tid >> 4;
        const int n0 = nr << 2, c0 = cg << 2;
        u64 acc[2][4];
        #pragma unroll
        for (int p = 0; p < 2; ++p)
            #pragma unroll
            for (int cc = 0; cc < 4; ++cc) acc[p][cc] = 0ull;
        #pragma unroll 8
        for (int j = 0; j < 128; ++j) {
            const float* ar = &sm[OFF_QT + j * LDN + n0];
            u64 a0 = lds2(ar), a1 = lds2(ar + 2);
            float4 bv = *(const float4*)&sm[OFF_AT + j * LDP + c0];
            float bs[4] = {bv.x, bv.y, bv.z, bv.w};
            #pragma unroll
            for (int cc = 0; cc < 4; ++cc) {
                u64 bb = pk2(bs[cc]);
                acc[0][cc] = f2fma(a0, bb, acc[0][cc]);
                acc[1][cc] = f2fma(a1, bb, acc[1][cc]);
            }
        }
        float4 pb = *(const float4*)(proj_b + c0);
        float* ob = out + (size_t)b * 8192;
        #pragma unroll
        for (int p = 0; p < 2; ++p) {
            float lo0, hi0, lo1, hi1, lo2, hi2, lo3, hi3;
            upk2(acc[p][0], lo0, hi0); upk2(acc[p][1], lo1, hi1);
            upk2(acc[p][2], lo2, hi2); upk2(acc[p][3], lo3, hi3);
            *(float4*)&ob[(n0 + 2*p    ) * 128 + c0] =
                make_float4(lo0 + pb.x, lo1 + pb.y, lo2 + pb.z, lo3 + pb.w);
            *(float4*)&ob[(n0 + 2*p + 1) * 128 + c0] =
                make_float4(hi0 + pb.x, hi1 + pb.y, hi2 + pb.z, hi3 + pb.w);
        }
    }
}

extern "C" void kernel_launch(void* const* d_in, const int* in_sizes, int n_in,
                              void* d_out, int out_size)
{
    const float* x      = (const float*)d_in[0];
    const float* y      = (const float*)d_in[1];
    const float* P      = (const float*)d_in[2];
    const float* maskp  = (const float*)d_in[3];
    const float* qkv_w  = (const float*)d_in[4];
    const float* qkv_b  = (const float*)d_in[5];
    const float* proj_w = (const float*)d_in[6];
    const float* proj_b = (const float*)d_in[7];
    const float* lam    = (const float*)d_in[8];
    float* out = (float*)d_out;

    cudaFuncSetAttribute(wattn_kernel,
                         cudaFuncAttributeMaxDynamicSharedMemorySize, SMEM_BYTES);
    wattn_kernel<<<4096, 512, SMEM_BYTES>>>(x, y, P, maskp, qkv_w, qkv_b,
                                            proj_w, proj_b, lam, out);
}

// round 9
// speedup vs baseline: 1.0029x; 1.0029x over previous
#include <cuda_runtime.h>

// WindowAttention fused kernel, fp32 packed fma.rn.f32x2 (sm_103a).
// R7: all A-operands loaded as LDS.128 (float4) and repacked to f32x2 pairs,
//     halving the LDS instruction stream; deeper unrolls. 512 thr/CTA.

#define SCALE_F 0.17677669529663687f   // 32^-0.5

#define LDN 68     // leading dim for k-major [*][64] arrays (float4-aligned rows)
#define LDV 132    // v row-major [64][128] padded
#define LDW 260    // staged qkv_w chunk [16][256] padded
#define LDP 132    // p_t [128][128] padded

#define OFF_QT 0                        // q_t [128][LDN] (o_t aliases after GEMM2)
#define OFF_KT (128*LDN)                // k_t [128][LDN]
#define OFF_V  (2*128*LDN)              // v   [64][LDV]
#define OFF_AT (OFF_V + 64*LDV)         // y_t [128][LDN] -> attn_t [256][LDN] -> p_t [128][LDP]
#define OFF_W  (OFF_AT + 128*LDN)       // W double buffer: 2 x [16][LDW]
#define OFF_SC (OFF_AT + 256*LDN)       // softmax scratch [2][256]
#define SMEM_FLOATS (OFF_SC + 512)
#define SMEM_BYTES  (SMEM_FLOATS * 4)   // 175104 B

typedef unsigned long long u64;

__device__ __forceinline__ u64 pk2(float v) {
    u64 r; asm("mov.b64 %0, {%1, %1};" : "=l"(r) : "f"(v)); return r;
}
__device__ __forceinline__ u64 pkab(float lo, float hi) {
    u64 r; asm("mov.b64 %0, {%1, %2};" : "=l"(r) : "f"(lo), "f"(hi)); return r;
}
__device__ __forceinline__ u64 f2fma(u64 a, u64 b, u64 c) {
    u64 d; asm("fma.rn.f32x2 %0, %1, %2, %3;" : "=l"(d) : "l"(a), "l"(b), "l"(c)); return d;
}
__device__ __forceinline__ u64 f2add(u64 a, u64 b) {
    u64 d; asm("add.rn.f32x2 %0, %1, %2;" : "=l"(d) : "l"(a), "l"(b)); return d;
}
__device__ __forceinline__ void upk2(u64 v, float& lo, float& hi) {
    asm("mov.b64 {%0, %1}, %2;" : "=f"(lo), "=f"(hi) : "l"(v));
}

__global__ void __launch_bounds__(512, 1)
wattn_kernel(const float* __restrict__ x, const float* __restrict__ y,
             const float* __restrict__ P, const float* __restrict__ maskp,
             const float* __restrict__ qkv_w, const float* __restrict__ qkv_b,
             const float* __restrict__ proj_w, const float* __restrict__ proj_b,
             const float* __restrict__ lam_p, float* __restrict__ out)
{
    extern __shared__ float sm[];
    const int b   = blockIdx.x;
    const int tid = threadIdx.x;

    // ===== Phase 0: register 4x4 block transposes =====
    {
        const int h = tid >> 7, nb = (tid >> 3) & 15, db = tid & 7;
        const float* xb = x + (size_t)b * 8192 + h * 2048 + db * 4;
        float4 r0 = *(const float4*)(xb + (4 * nb + 0) * 32);
        float4 r1 = *(const float4*)(xb + (4 * nb + 1) * 32);
        float4 r2 = *(const float4*)(xb + (4 * nb + 2) * 32);
        float4 r3 = *(const float4*)(xb + (4 * nb + 3) * 32);
        float* qb = &sm[OFF_QT + (32 * h + 4 * db) * LDN + 4 * nb];
        *(float4*)(qb + 0 * LDN) = make_float4(r0.x*SCALE_F, r1.x*SCALE_F, r2.x*SCALE_F, r3.x*SCALE_F);
        *(float4*)(qb + 1 * LDN) = make_float4(r0.y*SCALE_F, r1.y*SCALE_F, r2.y*SCALE_F, r3.y*SCALE_F);
        *(float4*)(qb + 2 * LDN) = make_float4(r0.z*SCALE_F, r1.z*SCALE_F, r2.z*SCALE_F, r3.z*SCALE_F);
        *(float4*)(qb + 3 * LDN) = make_float4(r0.w*SCALE_F, r1.w*SCALE_F, r2.w*SCALE_F, r3.w*SCALE_F);
    }
    {
        const int nb = tid & 15, kb = tid >> 4;       // kb 0..31
        const float* yb = y + (size_t)b * 8192 + kb * 4;
        float4 r0 = *(const float4*)(yb + (4 * nb + 0) * 128);
        float4 r1 = *(const float4*)(yb + (4 * nb + 1) * 128);
        float4 r2 = *(const float4*)(yb + (4 * nb + 2) * 128);
        float4 r3 = *(const float4*)(yb + (4 * nb + 3) * 128);
        float* yt = &sm[OFF_AT + (4 * kb) * LDN + 4 * nb];
        *(float4*)(yt + 0 * LDN) = make_float4(r0.x, r1.x, r2.x, r3.x);
        *(float4*)(yt + 1 * LDN) = make_float4(r0.y, r1.y, r2.y, r3.y);
        *(float4*)(yt + 2 * LDN) = make_float4(r0.z, r1.z, r2.z, r3.z);
        *(float4*)(yt + 3 * LDN) = make_float4(r0.w, r1.w, r2.w, r3.w);
    }

    // ===== GEMM1: kv[n][c] = sum_k y_t[k][n] * qkv_w[c][k] + qkv_b[c] =====
    // Thread tile 8n x 4c; double-buffered weight staging; LDS.128 A-loads.
    {
        const int tc = tid >> 3, tr = tid & 7;
        const int c0 = tc << 2, r0 = tr << 3;
        const int cw = tid >> 1, hf = tid & 1;
        const float* wsrc = qkv_w + cw * 128 + 8 * hf;
        u64 acc[4][4];
        #pragma unroll
        for (int p = 0; p < 4; ++p)
            #pragma unroll
            for (int cc = 0; cc < 4; ++cc) acc[p][cc] = 0ull;

        {   // stage chunk 0
            float4 w0 = *(const float4*)(wsrc);
            float4 w1 = *(const float4*)(wsrc + 4);
            float wv[8] = {w0.x,w0.y,w0.z,w0.w, w1.x,w1.y,w1.z,w1.w};
            #pragma unroll
            for (int jj = 0; jj < 8; ++jj)
                sm[OFF_W + (8 * hf + jj) * LDW + cw] = wv[jj];
        }
        __syncthreads();

        #pragma unroll 1
        for (int ch = 0; ch < 8; ++ch) {
            const int kk0 = ch << 4;
            const int cur = OFF_W + (ch & 1) * (16 * LDW);
            float4 w0, w1;
            if (ch < 7) {
                w0 = *(const float4*)(wsrc + kk0 + 16);
                w1 = *(const float4*)(wsrc + kk0 + 20);
            }
            #pragma unroll 8
            for (int j = 0; j < 16; ++j) {
                const float* ar = &sm[OFF_AT + (kk0 + j) * LDN + r0];
                float4 af0 = *(const float4*)ar;
                float4 af1 = *(const float4*)(ar + 4);
                u64 a0 = pkab(af0.x, af0.y), a1 = pkab(af0.z, af0.w);
                u64 a2 = pkab(af1.x, af1.y), a3 = pkab(af1.z, af1.w);
                float4 bv = *(const float4*)&sm[cur + j * LDW + c0];
                float bs[4] = {bv.x, bv.y, bv.z, bv.w};
                #pragma unroll
                for (int cc = 0; cc < 4; ++cc) {
                    u64 bb = pk2(bs[cc]);
                    acc[0][cc] = f2fma(a0, bb, acc[0][cc]);
                    acc[1][cc] = f2fma(a1, bb, acc[1][cc]);
                    acc[2][cc] = f2fma(a2, bb, acc[2][cc]);
                    acc[3][cc] = f2fma(a3, bb, acc[3][cc]);
                }
            }
            if (ch < 7) {
                const int nxt = OFF_W + ((ch + 1) & 1) * (16 * LDW);
                float wv[8] = {w0.x,w0.y,w0.z,w0.w, w1.x,w1.y,w1.z,w1.w};
                #pragma unroll
                for (int jj = 0; jj < 8; ++jj)
                    sm[nxt + (8 * hf + jj) * LDW + cw] = wv[jj];
                __syncthreads();
            }
        }
        float4 b4 = *(const float4*)(qkv_b + c0);
        float bias[4] = {b4.x, b4.y, b4.z, b4.w};
        if (c0 < 128) {
            #pragma unroll
            for (int cc = 0; cc < 4; ++cc) {
                u64 bb = pk2(bias[cc]);
                #pragma unroll
                for (int p = 0; p < 4; ++p)
                    *(u64*)&sm[OFF_KT + (c0 + cc) * LDN + r0 + 2 * p] = f2add(acc[p][cc], bb);
            }
        } else {
            #pragma unroll
            for (int cc = 0; cc < 4; ++cc) {
                int c = c0 + cc - 128;
                #pragma unroll
                for (int p = 0; p < 4; ++p) {
                    float lo, hi; upk2(acc[p][cc], lo, hi);
                    sm[OFF_V + (r0 + 2 * p    ) * LDV + c] = lo + bias[cc];
                    sm[OFF_V + (r0 + 2 * p + 1) * LDV + c] = hi + bias[cc];
                }
            }
        }
    }
    __syncthreads();

    // ===== GEMM2: attn_t[h*64+m][n] = sum_d q_t[32h+d][n] * k_t[32h+d][m] =====
    {
        const int h = tid >> 7, rest = tid & 127;
        const int mg = rest >> 3, tr = rest & 7;
        const int m0 = mg << 2, r0 = tr << 3;
        u64 acc[4][4];
        #pragma unroll
        for (int p = 0; p < 4; ++p)
            #pragma unroll
            for (int cc = 0; cc < 4; ++cc) acc[p][cc] = 0ull;
        #pragma unroll 16
        for (int d = 0; d < 32; ++d) {
            const int row = (h << 5) + d;
            const float* ar = &sm[OFF_QT + row * LDN + r0];
            float4 af0 = *(const float4*)ar;
            float4 af1 = *(const float4*)(ar + 4);
            u64 a0 = pkab(af0.x, af0.y), a1 = pkab(af0.z, af0.w);
            u64 a2 = pkab(af1.x, af1.y), a3 = pkab(af1.z, af1.w);
            float4 bv = *(const float4*)&sm[OFF_KT + row * LDN + m0];
            float bs[4] = {bv.x, bv.y, bv.z, bv.w};
            #pragma unroll
            for (int cc = 0; cc < 4; ++cc) {
                u64 bb = pk2(bs[cc]);
                acc[0][cc] = f2fma(a0, bb, acc[0][cc]);
                acc[1][cc] = f2fma(a1, bb, acc[1][cc]);
                acc[2][cc] = f2fma(a2, bb, acc[2][cc]);
                acc[3][cc] = f2fma(a3, bb, acc[3][cc]);
            }
        }
        #pragma unroll
        for (int cc = 0; cc < 4; ++cc) {
            const int row = (h << 6) + m0 + cc;
            #pragma unroll
            for (int p = 0; p < 4; ++p)
                *(u64*)&sm[OFF_AT + row * LDN + r0 + 2 * p] = acc[p][cc];
        }
    }
    __syncthreads();

    // ===== Softmax over m with mask + lambda*P; 2 threads per column =====
    {
        const int col = tid & 255, half = tid >> 8;
        const int h = col >> 6, n = col & 63;
        const int m0 = half << 5;
        const float lam = lam_p[0];
        const int w = b & 2047;
        const float4* Pr = (const float4*)(P + ((((size_t)b * 4 + h) * 64 + n) * 64) + m0);
        const float4* Mr = (const float4*)(maskp + (((size_t)w * 64 + n) * 64) + m0);
        const int base = OFF_AT + ((h << 6) + m0) * LDN + n;
        float v[32];
        float s = 0.f;
        #pragma unroll
        for (int q = 0; q < 8; ++q) {
            float4 pv = Pr[q];
            float4 mv = Mr[q];
            float t0 = sm[base + (4*q+0)*LDN] + mv.x + lam * pv.x;
            float t1 = sm[base + (4*q+1)*LDN] + mv.y + lam * pv.y;
            float t2 = sm[base + (4*q+2)*LDN] + mv.z + lam * pv.z;
            float t3 = sm[base + (4*q+3)*LDN] + mv.w + lam * pv.w;
            v[4*q+0] = __expf(t0); v[4*q+1] = __expf(t1);
            v[4*q+2] = __expf(t2); v[4*q+3] = __expf(t3);
            s += v[4*q+0] + v[4*q+1] + v[4*q+2] + v[4*q+3];
        }
        sm[OFF_SC + (half << 8) + col] = s;
        __syncthreads();
        const float inv = 1.0f / (sm[OFF_SC + col] + sm[OFF_SC + 256 + col]);
        #pragma unroll
        for (int m = 0; m < 32; ++m) sm[base + m * LDN] = v[m] * inv;
    }
    __syncthreads();

    // ===== GEMM3: o_t[j][n] = sum_m attn_t[h*64+m][n] * v[m][j], h=j/32 =====
    {
        const int nr = tid & 15, jc = tid >> 4;
        const int n0 = nr << 2, j0 = jc << 2, h = jc >> 3;
        u64 acc[2][4];
        #pragma unroll
        for (int p = 0; p < 2; ++p)
            #pragma unroll
            for (int cc = 0; cc < 4; ++cc) acc[p][cc] = 0ull;
        #pragma unroll 16
        for (int m = 0; m < 64; ++m) {
            float4 af = *(const float4*)&sm[OFF_AT + ((h << 6) + m) * LDN + n0];
            u64 a0 = pkab(af.x, af.y), a1 = pkab(af.z, af.w);
            float4 bv = *(const float4*)&sm[OFF_V + m * LDV + j0];
            float bs[4] = {bv.x, bv.y, bv.z, bv.w};
            #pragma unroll
            for (int cc = 0; cc < 4; ++cc) {
                u64 bb = pk2(bs[cc]);
                acc[0][cc] = f2fma(a0, bb, acc[0][cc]);
                acc[1][cc] = f2fma(a1, bb, acc[1][cc]);
            }
        }
        #pragma unroll
        for (int cc = 0; cc < 4; ++cc)
            #pragma unroll
            for (int p = 0; p < 2; ++p)
                *(u64*)&sm[OFF_QT + (j0 + cc) * LDN + n0 + 2 * p] = acc[p][cc];
    }
    __syncthreads();

    // ===== Stage proj_w transposed: p_t[j][c] =====
    {
        const int c = tid >> 2, qq = tid & 3;
        const float* pr = proj_w + c * 128 + qq * 32;
        #pragma unroll
        for (int i = 0; i < 8; ++i) {
            float4 pv = ((const float4*)pr)[i];
            const int j = (qq << 5) + (i << 2);
            sm[OFF_AT + (j    ) * LDP + c] = pv.x;
            sm[OFF_AT + (j + 1) * LDP + c] = pv.y;
            sm[OFF_AT + (j + 2) * LDP + c] = pv.z;
            sm[OFF_AT + (j + 3) * LDP + c] = pv.w;
        }
    }
    __syncthreads();

    // ===== GEMM4: res[n][c] = sum_j o_t[j][n] * p_t[j][c] + proj_b[c] =====
    {
        const int nr = tid & 15, cg = tid >> 4;
        const int n0 = nr << 2, c0 = cg << 2;
        u64 acc[2][4];
        #pragma unroll
        for (int p = 0; p < 2; ++p)
            #pragma unroll
            for (int cc = 0; cc < 4; ++cc) acc[p][cc] = 0ull;
        #pragma unroll 16
        for (int j = 0; j < 128; ++j) {
            float4 af = *(const float4*)&sm[OFF_QT + j * LDN + n0];
            u64 a0 = pkab(af.x, af.y), a1 = pkab(af.z, af.w);
            float4 bv = *(const float4*)&sm[OFF_AT + j * LDP + c0];
            float bs[4] = {bv.x, bv.y, bv.z, bv.w};
            #pragma unroll
            for (int cc = 0; cc < 4; ++cc) {
                u64 bb = pk2(bs[cc]);
                acc[0][cc] = f2fma(a0, bb, acc[0][cc]);
                acc[1][cc] = f2fma(a1, bb, acc[1][cc]);
            }
        }
        float4 pb = *(const float4*)(proj_b + c0);
        float* ob = out + (size_t)b * 8192;
        #pragma unroll
        for (int p = 0; p < 2; ++p) {
            float lo0, hi0, lo1, hi1, lo2, hi2, lo3, hi3;
            upk2(acc[p][0], lo0, hi0); upk2(acc[p][1], lo1, hi1);
            upk2(acc[p][2], lo2, hi2); upk2(acc[p][3], lo3, hi3);
            *(float4*)&ob[(n0 + 2*p    ) * 128 + c0] =
                make_float4(lo0 + pb.x, lo1 + pb.y, lo2 + pb.z, lo3 + pb.w);
            *(float4*)&ob[(n0 + 2*p + 1) * 128 + c0] =
                make_float4(hi0 + pb.x, hi1 + pb.y, hi2 + pb.z, hi3 + pb.w);
        }
    }
}

extern "C" void kernel_launch(void* const* d_in, const int* in_sizes, int n_in,
                              void* d_out, int out_size)
{
    const float* x      = (const float*)d_in[0];
    const float* y      = (const float*)d_in[1];
    const float* P      = (const float*)d_in[2];
    const float* maskp  = (const float*)d_in[3];
    const float* qkv_w  = (const float*)d_in[4];
    const float* qkv_b  = (const float*)d_in[5];
    const float* proj_w = (const float*)d_in[6];
    const float* proj_b = (const float*)d_in[7];
    const float* lam    = (const float*)d_in[8];
    float* out = (float*)d_out;

    cudaFuncSetAttribute(wattn_kernel,
                         cudaFuncAttributeMaxDynamicSharedMemorySize, SMEM_BYTES);
    wattn_kernel<<<4096, 512, SMEM_BYTES>>>(x, y, P, maskp, qkv_w, qkv_b,
                                            proj_w, proj_b, lam, out);
}

// round 10
// speedup vs baseline: 1.2408x; 1.2371x over previous
#include <cuda_runtime.h>

// WindowAttention fused kernel, fp32 packed fma.rn.f32x2 (sm_103a).
// R9: bank-conflict-free column swizzle SW(c)=c+((c&32)>>3) on all k-major
//     [row][64] smem arrays; v stored k-major (unified transposed writeback).

#define SCALE_F 0.17677669529663687f   // 32^-0.5

#define LDN 68     // leading dim for k-major [*][64(+4 swizzle)] arrays
#define LDW 260    // staged qkv_w chunk [16][256] padded
#define LDP 132    // p_t [128][128] padded

#define SW(c) ((c) + (((c) & 32) >> 3))

#define OFF_QT 0                        // q_t [128][LDN] (o_t aliases after GEMM3)
#define OFF_KT (128*LDN)                // k_t [128][LDN]
#define OFF_V  (2*128*LDN)              // v_t [128][LDN]  (k-major: [c'][n])
#define OFF_AT (3*128*LDN)              // y_t [128][LDN] -> attn_t [256][LDN] -> p_t [128][LDP]
#define OFF_W  (OFF_AT + 128*LDN)       // W double buffer: 2 x [16][LDW]
#define OFF_SC (OFF_AT + 256*LDN)       // softmax scratch [2][256]
#define SMEM_FLOATS (OFF_SC + 512)
#define SMEM_BYTES  (SMEM_FLOATS * 4)   // 176128 B

typedef unsigned long long u64;

__device__ __forceinline__ u64 pk2(float v) {
    u64 r; asm("mov.b64 %0, {%1, %1};" : "=l"(r) : "f"(v)); return r;
}
__device__ __forceinline__ u64 pkab(float lo, float hi) {
    u64 r; asm("mov.b64 %0, {%1, %2};" : "=l"(r) : "f"(lo), "f"(hi)); return r;
}
__device__ __forceinline__ u64 f2fma(u64 a, u64 b, u64 c) {
    u64 d; asm("fma.rn.f32x2 %0, %1, %2, %3;" : "=l"(d) : "l"(a), "l"(b), "l"(c)); return d;
}
__device__ __forceinline__ u64 f2add(u64 a, u64 b) {
    u64 d; asm("add.rn.f32x2 %0, %1, %2;" : "=l"(d) : "l"(a), "l"(b)); return d;
}
__device__ __forceinline__ void upk2(u64 v, float& lo, float& hi) {
    asm("mov.b64 {%0, %1}, %2;" : "=f"(lo), "=f"(hi) : "l"(v));
}

__global__ void __launch_bounds__(512, 1)
wattn_kernel(const float* __restrict__ x, const float* __restrict__ y,
             const float* __restrict__ P, const float* __restrict__ maskp,
             const float* __restrict__ qkv_w, const float* __restrict__ qkv_b,
             const float* __restrict__ proj_w, const float* __restrict__ proj_b,
             const float* __restrict__ lam_p, float* __restrict__ out)
{
    extern __shared__ float sm[];
    const int b   = blockIdx.x;
    const int tid = threadIdx.x;

    // ===== Phase 0: register 4x4 block transposes (stores at swizzled cols) =====
    {
        const int h = tid >> 7, nb = (tid >> 3) & 15, db = tid & 7;
        const float* xb = x + (size_t)b * 8192 + h * 2048 + db * 4;
        float4 r0 = *(const float4*)(xb + (4 * nb + 0) * 32);
        float4 r1 = *(const float4*)(xb + (4 * nb + 1) * 32);
        float4 r2 = *(const float4*)(xb + (4 * nb + 2) * 32);
        float4 r3 = *(const float4*)(xb + (4 * nb + 3) * 32);
        float* qb = &sm[OFF_QT + (32 * h + 4 * db) * LDN + SW(4 * nb)];
        *(float4*)(qb + 0 * LDN) = make_float4(r0.x*SCALE_F, r1.x*SCALE_F, r2.x*SCALE_F, r3.x*SCALE_F);
        *(float4*)(qb + 1 * LDN) = make_float4(r0.y*SCALE_F, r1.y*SCALE_F, r2.y*SCALE_F, r3.y*SCALE_F);
        *(float4*)(qb + 2 * LDN) = make_float4(r0.z*SCALE_F, r1.z*SCALE_F, r2.z*SCALE_F, r3.z*SCALE_F);
        *(float4*)(qb + 3 * LDN) = make_float4(r0.w*SCALE_F, r1.w*SCALE_F, r2.w*SCALE_F, r3.w*SCALE_F);
    }
    {
        const int nb = tid & 15, kb = tid >> 4;       // kb 0..31
        const float* yb = y + (size_t)b * 8192 + kb * 4;
        float4 r0 = *(const float4*)(yb + (4 * nb + 0) * 128);
        float4 r1 = *(const float4*)(yb + (4 * nb + 1) * 128);
        float4 r2 = *(const float4*)(yb + (4 * nb + 2) * 128);
        float4 r3 = *(const float4*)(yb + (4 * nb + 3) * 128);
        float* yt = &sm[OFF_AT + (4 * kb) * LDN + SW(4 * nb)];
        *(float4*)(yt + 0 * LDN) = make_float4(r0.x, r1.x, r2.x, r3.x);
        *(float4*)(yt + 1 * LDN) = make_float4(r0.y, r1.y, r2.y, r3.y);
        *(float4*)(yt + 2 * LDN) = make_float4(r0.z, r1.z, r2.z, r3.z);
        *(float4*)(yt + 3 * LDN) = make_float4(r0.w, r1.w, r2.w, r3.w);
    }

    // ===== GEMM1: kv[n][c] = sum_k y_t[k][n] * qkv_w[c][k] + qkv_b[c] =====
    // Thread tile 8n x 4c; double-buffered weight staging; swizzled A-loads.
    {
        const int tc = tid >> 3, tr = tid & 7;
        const int c0 = tc << 2, r0 = tr << 3;
        const int r0s = SW(r0);
        const int cw = tid >> 1, hf = tid & 1;
        const float* wsrc = qkv_w + cw * 128 + 8 * hf;
        u64 acc[4][4];
        #pragma unroll
        for (int p = 0; p < 4; ++p)
            #pragma unroll
            for (int cc = 0; cc < 4; ++cc) acc[p][cc] = 0ull;

        {   // stage chunk 0
            float4 w0 = *(const float4*)(wsrc);
            float4 w1 = *(const float4*)(wsrc + 4);
            float wv[8] = {w0.x,w0.y,w0.z,w0.w, w1.x,w1.y,w1.z,w1.w};
            #pragma unroll
            for (int jj = 0; jj < 8; ++jj)
                sm[OFF_W + (8 * hf + jj) * LDW + cw] = wv[jj];
        }
        __syncthreads();

        #pragma unroll 1
        for (int ch = 0; ch < 8; ++ch) {
            const int kk0 = ch << 4;
            const int cur = OFF_W + (ch & 1) * (16 * LDW);
            float4 w0, w1;
            if (ch < 7) {
                w0 = *(const float4*)(wsrc + kk0 + 16);
                w1 = *(const float4*)(wsrc + kk0 + 20);
            }
            #pragma unroll 8
            for (int j = 0; j < 16; ++j) {
                const float* ar = &sm[OFF_AT + (kk0 + j) * LDN + r0s];
                float4 af0 = *(const float4*)ar;
                float4 af1 = *(const float4*)(ar + 4);
                u64 a0 = pkab(af0.x, af0.y), a1 = pkab(af0.z, af0.w);
                u64 a2 = pkab(af1.x, af1.y), a3 = pkab(af1.z, af1.w);
                float4 bv = *(const float4*)&sm[cur + j * LDW + c0];
                float bs[4] = {bv.x, bv.y, bv.z, bv.w};
                #pragma unroll
                for (int cc = 0; cc < 4; ++cc) {
                    u64 bb = pk2(bs[cc]);
                    acc[0][cc] = f2fma(a0, bb, acc[0][cc]);
                    acc[1][cc] = f2fma(a1, bb, acc[1][cc]);
                    acc[2][cc] = f2fma(a2, bb, acc[2][cc]);
                    acc[3][cc] = f2fma(a3, bb, acc[3][cc]);
                }
            }
            if (ch < 7) {
                const int nxt = OFF_W + ((ch + 1) & 1) * (16 * LDW);
                float wv[8] = {w0.x,w0.y,w0.z,w0.w, w1.x,w1.y,w1.z,w1.w};
                #pragma unroll
                for (int jj = 0; jj < 8; ++jj)
                    sm[nxt + (8 * hf + jj) * LDW + cw] = wv[jj];
                __syncthreads();
            }
        }
        // Unified transposed writeback: c<128 -> k_t[c][n], c>=128 -> v_t[c-128][n]
        float4 b4 = *(const float4*)(qkv_b + c0);
        float bias[4] = {b4.x, b4.y, b4.z, b4.w};
        const int dstbase = (c0 < 128) ? (OFF_KT + c0 * LDN)
                                       : (OFF_V + (c0 - 128) * LDN);
        #pragma unroll
        for (int cc = 0; cc < 4; ++cc) {
            u64 bb = pk2(bias[cc]);
            #pragma unroll
            for (int p = 0; p < 4; ++p)
                *(u64*)&sm[dstbase + cc * LDN + r0s + 2 * p] = f2add(acc[p][cc], bb);
        }
    }
    __syncthreads();

    // ===== GEMM2: attn_t[h*64+m][n] = sum_d q_t[32h+d][n] * k_t[32h+d][m] =====
    {
        const int h = tid >> 7, rest = tid & 127;
        const int mg = rest >> 3, tr = rest & 7;
        const int m0 = mg << 2, r0 = tr << 3;
        const int r0s = SW(r0), m0s = SW(m0);
        u64 acc[4][4];
        #pragma unroll
        for (int p = 0; p < 4; ++p)
            #pragma unroll
            for (int cc = 0; cc < 4; ++cc) acc[p][cc] = 0ull;
        #pragma unroll 8
        for (int d = 0; d < 32; ++d) {
            const int row = (h << 5) + d;
            const float* ar = &sm[OFF_QT + row * LDN + r0s];
            float4 af0 = *(const float4*)ar;
            float4 af1 = *(const float4*)(ar + 4);
            u64 a0 = pkab(af0.x, af0.y), a1 = pkab(af0.z, af0.w);
            u64 a2 = pkab(af1.x, af1.y), a3 = pkab(af1.z, af1.w);
            float4 bv = *(const float4*)&sm[OFF_KT + row * LDN + m0s];
            float bs[4] = {bv.x, bv.y, bv.z, bv.w};
            #pragma unroll
            for (int cc = 0; cc < 4; ++cc) {
                u64 bb = pk2(bs[cc]);
                acc[0][cc] = f2fma(a0, bb, acc[0][cc]);
                acc[1][cc] = f2fma(a1, bb, acc[1][cc]);
                acc[2][cc] = f2fma(a2, bb, acc[2][cc]);
                acc[3][cc] = f2fma(a3, bb, acc[3][cc]);
            }
        }
        #pragma unroll
        for (int cc = 0; cc < 4; ++cc) {
            const int row = (h << 6) + m0 + cc;
            #pragma unroll
            for (int p = 0; p < 4; ++p)
                *(u64*)&sm[OFF_AT + row * LDN + r0s + 2 * p] = acc[p][cc];
        }
    }
    __syncthreads();

    // ===== Softmax over m with mask + lambda*P; 2 threads per column =====
    {
        const int col = tid & 255, half = tid >> 8;
        const int h = col >> 6, n = col & 63;
        const int m0 = half << 5;
        const int ns = SW(n);
        const float lam = lam_p[0];
        const int w = b & 2047;
        const float4* Pr = (const float4*)(P + ((((size_t)b * 4 + h) * 64 + n) * 64) + m0);
        const float4* Mr = (const float4*)(maskp + (((size_t)w * 64 + n) * 64) + m0);
        const int base = OFF_AT + ((h << 6) + m0) * LDN + ns;
        float v[32];
        float s = 0.f;
        #pragma unroll
        for (int q = 0; q < 8; ++q) {
            float4 pv = Pr[q];
            float4 mv = Mr[q];
            float t0 = sm[base + (4*q+0)*LDN] + mv.x + lam * pv.x;
            float t1 = sm[base + (4*q+1)*LDN] + mv.y + lam * pv.y;
            float t2 = sm[base + (4*q+2)*LDN] + mv.z + lam * pv.z;
            float t3 = sm[base + (4*q+3)*LDN] + mv.w + lam * pv.w;
            v[4*q+0] = __expf(t0); v[4*q+1] = __expf(t1);
            v[4*q+2] = __expf(t2); v[4*q+3] = __expf(t3);
            s += v[4*q+0] + v[4*q+1] + v[4*q+2] + v[4*q+3];
        }
        sm[OFF_SC + (half << 8) + col] = s;
        __syncthreads();
        const float inv = 1.0f / (sm[OFF_SC + col] + sm[OFF_SC + 256 + col]);
        #pragma unroll
        for (int m = 0; m < 32; ++m) sm[base + m * LDN] = v[m] * inv;
    }
    __syncthreads();

    // ===== GEMM3: o_t[j][n] = sum_m attn_t[h*64+m][n] * v_t[j][m], h=j/32 =====
    {
        const int nr = tid & 15, jc = tid >> 4;
        const int n0 = nr << 2, j0 = jc << 2, h = jc >> 3;
        const int n0s = SW(n0);
        u64 acc[2][4];
        #pragma unroll
        for (int p = 0; p < 2; ++p)
            #pragma unroll
            for (int cc = 0; cc < 4; ++cc) acc[p][cc] = 0ull;
        #pragma unroll 16
        for (int m = 0; m < 64; ++m) {
            const int ms = SW(m);
            float4 af = *(const float4*)&sm[OFF_AT + ((h << 6) + m) * LDN + n0s];
            u64 a0 = pkab(af.x, af.y), a1 = pkab(af.z, af.w);
            #pragma unroll
            for (int cc = 0; cc < 4; ++cc) {
                u64 bb = pk2(sm[OFF_V + (j0 + cc) * LDN + ms]);
                acc[0][cc] = f2fma(a0, bb, acc[0][cc]);
                acc[1][cc] = f2fma(a1, bb, acc[1][cc]);
            }
        }
        #pragma unroll
        for (int cc = 0; cc < 4; ++cc)
            #pragma unroll
            for (int p = 0; p < 2; ++p)
                *(u64*)&sm[OFF_QT + (j0 + cc) * LDN + n0s + 2 * p] = acc[p][cc];
    }
    __syncthreads();

    // ===== Stage proj_w transposed: p_t[j][c] (aliases dead attn region) =====
    {
        const int c = tid >> 2, qq = tid & 3;
        const float* pr = proj_w + c * 128 + qq * 32;
        #pragma unroll
        for (int i = 0; i < 8; ++i) {
            float4 pv = ((const float4*)pr)[i];
            const int j = (qq << 5) + (i << 2);
            sm[OFF_AT + (j    ) * LDP + c] = pv.x;
            sm[OFF_AT + (j + 1) * LDP + c] = pv.y;
            sm[OFF_AT + (j + 2) * LDP + c] = pv.z;
            sm[OFF_AT + (j + 3) * LDP + c] = pv.w;
        }
    }
    __syncthreads();

    // ===== GEMM4: res[n][c] = sum_j o_t[j][n] * p_t[j][c] + proj_b[c] =====
    {
        const int nr = tid & 15, cg = tid >> 4;
        const int n0 = nr << 2, c0 = cg << 2;
        const int n0s = SW(n0);
        u64 acc[2][4];
        #pragma unroll
        for (int p = 0; p < 2; ++p)
            #pragma unroll
            for (int cc = 0; cc < 4; ++cc) acc[p][cc] = 0ull;
        #pragma unroll 16
        for (int j = 0; j < 128; ++j) {
            float4 af = *(const float4*)&sm[OFF_QT + j * LDN + n0s];
            u64 a0 = pkab(af.x, af.y), a1 = pkab(af.z, af.w);
            float4 bv = *(const float4*)&sm[OFF_AT + j * LDP + c0];
            float bs[4] = {bv.x, bv.y, bv.z, bv.w};
            #pragma unroll
            for (int cc = 0; cc < 4; ++cc) {
                u64 bb = pk2(bs[cc]);
                acc[0][cc] = f2fma(a0, bb, acc[0][cc]);
                acc[1][cc] = f2fma(a1, bb, acc[1][cc]);
            }
        }
        float4 pb = *(const float4*)(proj_b + c0);
        float* ob = out + (size_t)b * 8192;
        #pragma unroll
        for (int p = 0; p < 2; ++p) {
            float lo0, hi0, lo1, hi1, lo2, hi2, lo3, hi3;
            upk2(acc[p][0], lo0, hi0); upk2(acc[p][1], lo1, hi1);
            upk2(acc[p][2], lo2, hi2); upk2(acc[p][3], lo3, hi3);
            *(float4*)&ob[(n0 + 2*p    ) * 128 + c0] =
                make_float4(lo0 + pb.x, lo1 + pb.y, lo2 + pb.z, lo3 + pb.w);
            *(float4*)&ob[(n0 + 2*p + 1) * 128 + c0] =
                make_float4(hi0 + pb.x, hi1 + pb.y, hi2 + pb.z, hi3 + pb.w);
        }
    }
}

extern "C" void kernel_launch(void* const* d_in, const int* in_sizes, int n_in,
                              void* d_out, int out_size)
{
    const float* x      = (const float*)d_in[0];
    const float* y      = (const float*)d_in[1];
    const float* P      = (const float*)d_in[2];
    const float* maskp  = (const float*)d_in[3];
    const float* qkv_w  = (const float*)d_in[4];
    const float* qkv_b  = (const float*)d_in[5];
    const float* proj_w = (const float*)d_in[6];
    const float* proj_b = (const float*)d_in[7];
    const float* lam    = (const float*)d_in[8];
    float* out = (float*)d_out;

    cudaFuncSetAttribute(wattn_kernel,
                         cudaFuncAttributeMaxDynamicSharedMemorySize, SMEM_BYTES);
    wattn_kernel<<<4096, 512, SMEM_BYTES>>>(x, y, P, maskp, qkv_w, qkv_b,
                                            proj_w, proj_b, lam, out);
}